// round 10
// baseline (speedup 1.0000x reference)
#include <cuda_runtime.h>
#include <cuda_bf16.h>
#include <cstdint>

// Problem constants
#define BB   2
#define SS   2048
#define DIM  2048
#define NH   16
#define DH   128
#define LKV  512
#define LQ   1024
#define MR   (BB*SS)    // 4096
#define HD   (NH*DH)    // 2048

// fp32 scratch
__device__ float g_qr [MR*(size_t)HD];
__device__ float g_kr [MR*(size_t)HD];
__device__ float g_v  [MR*(size_t)HD];
__device__ float g_sc [(size_t)BB*NH*SS*SS];   // 512 MB scores

// bf16 hi/lo split buffers
__device__ __nv_bfloat16 g_x_h  [MR*(size_t)DIM],  g_x_l  [MR*(size_t)DIM];
__device__ __nv_bfloat16 g_wlq_h [(size_t)LQ*DIM],  g_wlq_l [(size_t)LQ*DIM];
__device__ __nv_bfloat16 g_wlkv_h[(size_t)LKV*DIM], g_wlkv_l[(size_t)LKV*DIM];
__device__ __nv_bfloat16 g_wq_h [(size_t)HD*LQ],   g_wq_l [(size_t)HD*LQ];
__device__ __nv_bfloat16 g_wqr_h[(size_t)HD*LQ],   g_wqr_l[(size_t)HD*LQ];
__device__ __nv_bfloat16 g_wk_h [(size_t)HD*LKV],  g_wk_l [(size_t)HD*LKV];
__device__ __nv_bfloat16 g_wv_h [(size_t)HD*LKV],  g_wv_l [(size_t)HD*LKV];
__device__ __nv_bfloat16 g_wkr_h[(size_t)HD*DIM],  g_wkr_l[(size_t)HD*DIM];
__device__ __nv_bfloat16 g_wo_h [(size_t)DIM*HD],  g_wo_l [(size_t)DIM*HD];
__device__ __nv_bfloat16 g_cq_h [MR*(size_t)LQ],   g_cq_l [MR*(size_t)LQ];
__device__ __nv_bfloat16 g_ckv_h[MR*(size_t)LKV],  g_ckv_l[MR*(size_t)LKV];
__device__ __nv_bfloat16 g_qa_h [MR*(size_t)HD],   g_qa_l [MR*(size_t)HD];
__device__ __nv_bfloat16 g_qrs_h[MR*(size_t)HD],   g_qrs_l[MR*(size_t)HD];
__device__ __nv_bfloat16 g_ka_h [MR*(size_t)HD],   g_ka_l [MR*(size_t)HD];
__device__ __nv_bfloat16 g_krs_h[MR*(size_t)HD],   g_krs_l[MR*(size_t)HD];
__device__ __nv_bfloat16 g_vt_h [(size_t)BB*NH*DH*SS], g_vt_l [(size_t)BB*NH*DH*SS];
__device__ __nv_bfloat16 g_p_h  [(size_t)BB*NH*SS*SS], g_p_l  [(size_t)BB*NH*SS*SS];
__device__ __nv_bfloat16 g_att_h[MR*(size_t)HD],   g_att_l[MR*(size_t)HD];

// ---------------------------------------------------------------------------
// Helpers
// ---------------------------------------------------------------------------
__device__ __forceinline__ uint32_t smem_u32(const void* p) {
    uint32_t a;
    asm("{ .reg .u64 t; cvta.to.shared.u64 t, %1; cvt.u32.u64 %0, t; }" : "=r"(a) : "l"(p));
    return a;
}
__device__ __forceinline__ void ldm_x4(uint32_t addr, uint32_t r[4]) {
    asm volatile("ldmatrix.sync.aligned.m8n8.x4.shared.b16 {%0,%1,%2,%3}, [%4];"
                 : "=r"(r[0]), "=r"(r[1]), "=r"(r[2]), "=r"(r[3]) : "r"(addr));
}
__device__ __forceinline__ void mma16816(float c[4], const uint32_t a[4],
                                         uint32_t b0, uint32_t b1) {
    asm volatile(
        "mma.sync.aligned.m16n8k16.row.col.f32.bf16.bf16.f32 "
        "{%0,%1,%2,%3}, {%4,%5,%6,%7}, {%8,%9}, {%0,%1,%2,%3};"
        : "+f"(c[0]), "+f"(c[1]), "+f"(c[2]), "+f"(c[3])
        : "r"(a[0]), "r"(a[1]), "r"(a[2]), "r"(a[3]), "r"(b0), "r"(b1));
}
__device__ __forceinline__ uint32_t packbf(float a, float b) {
    uint32_t r;
    asm("cvt.rn.satfinite.bf16x2.f32 %0, %1, %2;" : "=r"(r) : "f"(b), "f"(a));
    return r;
}
__device__ __forceinline__ float lo_of(uint32_t h) { return __uint_as_float(h << 16); }
__device__ __forceinline__ float hi_of(uint32_t h) { return __uint_as_float(h & 0xFFFF0000u); }

__device__ __forceinline__ void cp16(uint32_t dst, const void* src) {
    asm volatile("cp.async.cg.shared.global [%0], [%1], 16;" :: "r"(dst), "l"(src) : "memory");
}
#define CP_COMMIT asm volatile("cp.async.commit_group;" ::: "memory")
#define CP_WAIT0  asm volatile("cp.async.wait_group 0;" ::: "memory")
#define CP_WAIT1  asm volatile("cp.async.wait_group 1;" ::: "memory")

// SMEM per stage: A_hi[128x32], A_lo, B_hi[64x32], B_lo; pitch 80B (64B data)
#define PITCH    80
#define OF_ALO   10240
#define OF_BHI   20480
#define OF_BLO   25600
#define STAGE_SZ 30720
#define NSTAGE   2
#define SMEMSZ   (NSTAGE*STAGE_SZ)     // 61440 -> 2+ CTAs/SM

// ---------------------------------------------------------------------------
// bgemm: C = alpha * A * B^T [+ bias], pre-split bf16 hi/lo inputs.
//   CTA tile 128(M) x 64(N), 256 threads = 8 warps (4M x 2N of 32x32).
//   DUAL: continue accumulating A2 * B2^T. SPLITOUT: bf16 hi/lo output.
//   Batched via grid.z. Grid (N/64, M/128, Z). 2-stage cp.async pipeline.
//   3-product bf16 emulation => fp32-level accuracy.
// ---------------------------------------------------------------------------
template<bool BIAS, bool DUAL, bool SPLITOUT>
__global__ __launch_bounds__(256)
void bgemm(int K,
           const __nv_bfloat16* __restrict__ Ah, const __nv_bfloat16* __restrict__ Al,
           int lda, long long sAb, long long sAz,
           const __nv_bfloat16* __restrict__ Bh, const __nv_bfloat16* __restrict__ Bl,
           int ldb, long long sBb, long long sBz,
           const __nv_bfloat16* __restrict__ A2h, const __nv_bfloat16* __restrict__ A2l,
           const __nv_bfloat16* __restrict__ B2h, const __nv_bfloat16* __restrict__ B2l,
           float* __restrict__ C, int ldc, long long sCb, long long sCz,
           const float* __restrict__ bias, float alpha, int Hdiv,
           __nv_bfloat16* __restrict__ Chi, __nv_bfloat16* __restrict__ Clo)
{
    extern __shared__ __align__(128) char smc[];
    const uint32_t smb = smem_u32(smc);
    const int tid  = threadIdx.x;
    const int lane = tid & 31;
    const int wid  = tid >> 5;
    const int wm   = (wid & 3) * 32;        // warp M offset (0..96)
    const int wn   = (wid >> 2) * 32;       // warp N offset (0 or 32)

    int z = blockIdx.z;
    int zb = z / Hdiv, zh = z - zb * Hdiv;
    const long long offA = zb * sAb + zh * sAz;
    const long long offB = zb * sBb + zh * sBz;
    Ah += offA; Al += offA;
    Bh += offB; Bl += offB;
    if (DUAL) { A2h += offA; A2l += offA; B2h += offB; B2l += offB; }
    const long long offC = zb * sCb + zh * sCz;
    if (SPLITOUT) { Chi += offC; Clo += offC; }
    else          { C   += offC; }

    // staging: A tile 128 rows x 32 k: 2 threads/row, 32B (16 bf16) each
    //          B tile  64 rows x 32 k: 4 threads/row, 16B ( 8 bf16) each
    const int arow = tid >> 1;
    const int aseg = (tid & 1) * 16;            // bf16 elems
    const int brow = tid >> 2;
    const int bseg = (tid & 3) * 8;             // bf16 elems
    const long long aoff = (long long)(blockIdx.y * 128 + arow) * lda + aseg;
    const long long boff = (long long)(blockIdx.x * 64 + brow) * ldb + bseg;
    const uint32_t dstA = smb + arow * PITCH + aseg * 2;
    const uint32_t dstB = smb + OF_BHI + brow * PITCH + bseg * 2;

    float acc[2][4][4];
#pragma unroll
    for (int i = 0; i < 2; i++)
#pragma unroll
        for (int j = 0; j < 4; j++)
#pragma unroll
            for (int k = 0; k < 4; k++) acc[i][j][k] = 0.f;

    const int nch   = K >> 5;
    const int total = DUAL ? nch * 2 : nch;

    auto issue = [&](int c) {
        const __nv_bfloat16 *ah = Ah, *al = Al, *bh = Bh, *bl = Bl;
        int cc = c;
        if (DUAL && c >= nch) { ah = A2h; al = A2l; bh = B2h; bl = B2l; cc = c - nch; }
        const long long ka = aoff + cc * 32;
        const long long kb = boff + cc * 32;
        const uint32_t stg = (c & (NSTAGE - 1)) * STAGE_SZ;
        cp16(dstA + stg,               ah + ka);
        cp16(dstA + stg + 16,          ah + ka + 8);
        cp16(dstA + stg + OF_ALO,      al + ka);
        cp16(dstA + stg + OF_ALO + 16, al + ka + 8);
        cp16(dstB + stg,               bh + kb);
        cp16(dstB + stg + (OF_BLO - OF_BHI), bl + kb);
    };

    auto COMPUTE = [&](int s) {
        const uint32_t sa = smb + s * STAGE_SZ;
#pragma unroll
        for (int ks = 0; ks < 2; ++ks) {
            const uint32_t colb = ks * 32;
            uint32_t ahi[2][4], alo[2][4], bhi[2][4], blo[2][4];
#pragma unroll
            for (int mt = 0; mt < 2; ++mt) {
                uint32_t addr = sa +
                    (wm + mt * 16 + (lane & 15)) * PITCH + colb + (lane >> 4) * 16;
                ldm_x4(addr, ahi[mt]);
                ldm_x4(addr + OF_ALO, alo[mt]);
            }
#pragma unroll
            for (int np = 0; np < 2; ++np) {
                uint32_t addr = sa + OF_BHI +
                    (wn + np * 16 + (lane & 7) + ((lane >> 4) << 3)) * PITCH +
                    colb + ((lane >> 3) & 1) * 16;
                ldm_x4(addr, bhi[np]);
                ldm_x4(addr + (OF_BLO - OF_BHI), blo[np]);
            }
#pragma unroll
            for (int mt = 0; mt < 2; ++mt)
#pragma unroll
                for (int nt = 0; nt < 4; ++nt) {
                    uint32_t b0h = bhi[nt >> 1][(nt & 1) * 2];
                    uint32_t b1h = bhi[nt >> 1][(nt & 1) * 2 + 1];
                    uint32_t b0l = blo[nt >> 1][(nt & 1) * 2];
                    uint32_t b1l = blo[nt >> 1][(nt & 1) * 2 + 1];
                    mma16816(acc[mt][nt], ahi[mt], b0h, b1h);
                    mma16816(acc[mt][nt], ahi[mt], b0l, b1l);
                    mma16816(acc[mt][nt], alo[mt], b0h, b1h);
                }
        }
    };

    // 2-stage pipeline, one sync per chunk
    issue(0); CP_COMMIT;
    for (int c = 0; c < total; ++c) {
        if (c + 1 < total) { issue(c + 1); CP_COMMIT; CP_WAIT1; } else { CP_WAIT0; }
        __syncthreads();
        COMPUTE(c & (NSTAGE - 1));
        __syncthreads();
    }

    // epilogue
    const int g = lane >> 2, t = lane & 3;
#pragma unroll
    for (int mt = 0; mt < 2; ++mt) {
        const int r0 = blockIdx.y * 128 + wm + mt * 16 + g;
#pragma unroll
        for (int nt = 0; nt < 4; ++nt) {
            const int col = blockIdx.x * 64 + wn + nt * 8 + t * 2;
            float b0 = 0.f, b1 = 0.f;
            if (BIAS) { b0 = bias[col]; b1 = bias[col + 1]; }
            float2 v0, v1;
            v0.x = alpha * acc[mt][nt][0] + b0;
            v0.y = alpha * acc[mt][nt][1] + b1;
            v1.x = alpha * acc[mt][nt][2] + b0;
            v1.y = alpha * acc[mt][nt][3] + b1;
            if (SPLITOUT) {
                uint32_t h0 = packbf(v0.x, v0.y);
                uint32_t l0 = packbf(v0.x - lo_of(h0), v0.y - hi_of(h0));
                uint32_t h1 = packbf(v1.x, v1.y);
                uint32_t l1 = packbf(v1.x - lo_of(h1), v1.y - hi_of(h1));
                *(uint32_t*)&Chi[(long long)r0 * ldc + col] = h0;
                *(uint32_t*)&Clo[(long long)r0 * ldc + col] = l0;
                *(uint32_t*)&Chi[(long long)(r0 + 8) * ldc + col] = h1;
                *(uint32_t*)&Clo[(long long)(r0 + 8) * ldc + col] = l1;
            } else {
                *(float2*)&C[(long long)r0 * ldc + col] = v0;
                *(float2*)&C[(long long)(r0 + 8) * ldc + col] = v1;
            }
        }
    }
}

// ---------------------------------------------------------------------------
// Split fp32 -> bf16 hi/lo, 9 jobs in one launch (grid.y selects job)
// ---------------------------------------------------------------------------
struct SplitJob  { const float* s; __nv_bfloat16* h; __nv_bfloat16* l; int n4; };
struct SplitJobs { SplitJob j[9]; };

__global__ void split_all(SplitJobs js)
{
    SplitJob job = js.j[blockIdx.y];
    int i = blockIdx.x * blockDim.x + threadIdx.x;
    if (i >= job.n4) return;
    float4 v = ((const float4*)job.s)[i];
    uint32_t h0 = packbf(v.x, v.y), h1 = packbf(v.z, v.w);
    uint32_t l0 = packbf(v.x - lo_of(h0), v.y - hi_of(h0));
    uint32_t l1 = packbf(v.z - lo_of(h1), v.w - hi_of(h1));
    ((uint2*)job.h)[i] = make_uint2(h0, h1);
    ((uint2*)job.l)[i] = make_uint2(l0, l1);
}

// ---------------------------------------------------------------------------
// RoPE + split: read fp32 [B*S, H*DH], rotate, write bf16 hi/lo
// ---------------------------------------------------------------------------
__global__ void rope_split(const float* __restrict__ src,
                           __nv_bfloat16* __restrict__ dh,
                           __nv_bfloat16* __restrict__ dl,
                           const float* __restrict__ fc,
                           const float* __restrict__ fs)
{
    long long idx = (long long)blockIdx.x * blockDim.x + threadIdx.x;
    const long long total = (long long)MR * NH * (DH / 2);
    if (idx >= total) return;
    int i = (int)(idx & 63);
    long long t2 = idx >> 6;
    int h = (int)(t2 % NH);
    long long row = t2 / NH;
    int s = (int)(row % SS);
    float c  = fc[s * 64 + i];
    float sn = fs[s * 64 + i];
    size_t off = (size_t)row * HD + h * DH + 2 * i;
    float e = src[off], o = src[off + 1];
    float e2 = e * c - o * sn;
    float o2 = e * sn + o * c;
    uint32_t hi = packbf(e2, o2);
    uint32_t lo = packbf(e2 - lo_of(hi), o2 - hi_of(hi));
    *(uint32_t*)&dh[off] = hi;
    *(uint32_t*)&dl[off] = lo;
}

// ---------------------------------------------------------------------------
// Transpose V + split: vt[z*DH + d][s] = v[(b*SS+s)*HD + h*DH + d]
// ---------------------------------------------------------------------------
__global__ void transpose_split(const float* __restrict__ v,
                                __nv_bfloat16* __restrict__ vth,
                                __nv_bfloat16* __restrict__ vtl)
{
    __shared__ float t[32][33];
    int z = blockIdx.z;
    int b = z / NH, h = z - b * NH;
    int s0 = blockIdx.y * 32, d0 = blockIdx.x * 32;
    int x = threadIdx.x, y = threadIdx.y;
#pragma unroll
    for (int i = 0; i < 32; i += 8)
        t[y + i][x] = v[((long long)(b * SS + s0 + y + i)) * HD + h * DH + d0 + x];
    __syncthreads();
#pragma unroll
    for (int i = 0; i < 32; i += 8) {
        float val = t[x][y + i];
        __nv_bfloat16 hb = __float2bfloat16(val);
        __nv_bfloat16 lb = __float2bfloat16(val - __bfloat162float(hb));
        size_t off = ((size_t)(z * DH + d0 + y + i)) * SS + s0 + x;
        vth[off] = hb;
        vtl[off] = lb;
    }
}

// ---------------------------------------------------------------------------
// Softmax + split: read fp32 score row (2048), write normalized P bf16 hi/lo.
// ---------------------------------------------------------------------------
__global__ __launch_bounds__(256) void softmax_split(const float* __restrict__ S,
                                                     __nv_bfloat16* __restrict__ Ph,
                                                     __nv_bfloat16* __restrict__ Pl)
{
    const float* p = S + (long long)blockIdx.x * SS;
    uint32_t* oh = (uint32_t*)(Ph + (long long)blockIdx.x * SS);
    uint32_t* ol = (uint32_t*)(Pl + (long long)blockIdx.x * SS);
    const int t = threadIdx.x;
    __shared__ float red[8];

    float2 v[4];
#pragma unroll
    for (int j = 0; j < 4; ++j) v[j] = *(const float2*)&p[2 * t + 512 * j];

    float m = fmaxf(v[0].x, v[0].y);
#pragma unroll
    for (int j = 1; j < 4; ++j) m = fmaxf(m, fmaxf(v[j].x, v[j].y));
#pragma unroll
    for (int o = 16; o > 0; o >>= 1) m = fmaxf(m, __shfl_xor_sync(~0u, m, o));
    if ((t & 31) == 0) red[t >> 5] = m;
    __syncthreads();
    if (t < 32) {
        float mm = red[t & 7];
#pragma unroll
        for (int o = 4; o > 0; o >>= 1) mm = fmaxf(mm, __shfl_xor_sync(~0u, mm, o));
        if (t == 0) red[0] = mm;
    }
    __syncthreads();
    m = red[0];
    __syncthreads();

    float sum = 0.f;
#pragma unroll
    for (int j = 0; j < 4; ++j) {
        v[j].x = __expf(v[j].x - m);
        v[j].y = __expf(v[j].y - m);
        sum += v[j].x + v[j].y;
    }
#pragma unroll
    for (int o = 16; o > 0; o >>= 1) sum += __shfl_xor_sync(~0u, sum, o);
    if ((t & 31) == 0) red[t >> 5] = sum;
    __syncthreads();
    if (t < 32) {
        float ss = red[t & 7];
#pragma unroll
        for (int o = 4; o > 0; o >>= 1) ss += __shfl_xor_sync(~0u, ss, o);
        if (t == 0) red[0] = ss;
    }
    __syncthreads();
    const float inv = 1.0f / red[0];
#pragma unroll
    for (int j = 0; j < 4; ++j) {
        float p0 = v[j].x * inv, p1 = v[j].y * inv;
        uint32_t h = packbf(p0, p1);
        uint32_t l = packbf(p0 - lo_of(h), p1 - hi_of(h));
        oh[t + 256 * j] = h;
        ol[t + 256 * j] = l;
    }
}

// ---------------------------------------------------------------------------

extern "C" void kernel_launch(void* const* d_in, const int* in_sizes, int n_in,
                              void* d_out, int out_size)
{
    const float* x    = (const float*)d_in[0];
    const float* fc   = (const float*)d_in[1];
    const float* fs   = (const float*)d_in[2];
    const float* w_lq = (const float*)d_in[3];
    const float* w_lkv= (const float*)d_in[4];
    const float* w_q  = (const float*)d_in[5];
    const float* w_k  = (const float*)d_in[6];
    const float* w_v  = (const float*)d_in[7];
    const float* w_qr = (const float*)d_in[8];
    const float* b_qr = (const float*)d_in[9];
    const float* w_kr = (const float*)d_in[10];
    const float* b_kr = (const float*)d_in[11];
    const float* w_o  = (const float*)d_in[12];
    const float* b_o  = (const float*)d_in[13];
    float* out = (float*)d_out;

    float *qr, *kr, *vv, *sc;
    cudaGetSymbolAddress((void**)&qr, g_qr);
    cudaGetSymbolAddress((void**)&kr, g_kr);
    cudaGetSymbolAddress((void**)&vv, g_v);
    cudaGetSymbolAddress((void**)&sc, g_sc);

    __nv_bfloat16 *xh, *xl, *wlqh, *wlql, *wlkvh, *wlkvl, *wqh, *wql, *wqrh, *wqrl;
    __nv_bfloat16 *wkh, *wkl, *wvh, *wvl, *wkrh, *wkrl, *woh, *wol;
    __nv_bfloat16 *cqh, *cql, *ckvh, *ckvl, *qah, *qal, *qrh, *qrl, *kah, *kal;
    __nv_bfloat16 *krh, *krl, *vth, *vtl, *ph, *pl, *atth, *attl;
    cudaGetSymbolAddress((void**)&xh,    g_x_h);   cudaGetSymbolAddress((void**)&xl,    g_x_l);
    cudaGetSymbolAddress((void**)&wlqh,  g_wlq_h); cudaGetSymbolAddress((void**)&wlql,  g_wlq_l);
    cudaGetSymbolAddress((void**)&wlkvh, g_wlkv_h);cudaGetSymbolAddress((void**)&wlkvl, g_wlkv_l);
    cudaGetSymbolAddress((void**)&wqh,   g_wq_h);  cudaGetSymbolAddress((void**)&wql,   g_wq_l);
    cudaGetSymbolAddress((void**)&wqrh,  g_wqr_h); cudaGetSymbolAddress((void**)&wqrl,  g_wqr_l);
    cudaGetSymbolAddress((void**)&wkh,   g_wk_h);  cudaGetSymbolAddress((void**)&wkl,   g_wk_l);
    cudaGetSymbolAddress((void**)&wvh,   g_wv_h);  cudaGetSymbolAddress((void**)&wvl,   g_wv_l);
    cudaGetSymbolAddress((void**)&wkrh,  g_wkr_h); cudaGetSymbolAddress((void**)&wkrl,  g_wkr_l);
    cudaGetSymbolAddress((void**)&woh,   g_wo_h);  cudaGetSymbolAddress((void**)&wol,   g_wo_l);
    cudaGetSymbolAddress((void**)&cqh,   g_cq_h);  cudaGetSymbolAddress((void**)&cql,   g_cq_l);
    cudaGetSymbolAddress((void**)&ckvh,  g_ckv_h); cudaGetSymbolAddress((void**)&ckvl,  g_ckv_l);
    cudaGetSymbolAddress((void**)&qah,   g_qa_h);  cudaGetSymbolAddress((void**)&qal,   g_qa_l);
    cudaGetSymbolAddress((void**)&qrh,   g_qrs_h); cudaGetSymbolAddress((void**)&qrl,   g_qrs_l);
    cudaGetSymbolAddress((void**)&kah,   g_ka_h);  cudaGetSymbolAddress((void**)&kal,   g_ka_l);
    cudaGetSymbolAddress((void**)&krh,   g_krs_h); cudaGetSymbolAddress((void**)&krl,   g_krs_l);
    cudaGetSymbolAddress((void**)&vth,   g_vt_h);  cudaGetSymbolAddress((void**)&vtl,   g_vt_l);
    cudaGetSymbolAddress((void**)&ph,    g_p_h);   cudaGetSymbolAddress((void**)&pl,    g_p_l);
    cudaGetSymbolAddress((void**)&atth,  g_att_h); cudaGetSymbolAddress((void**)&attl,  g_att_l);

    cudaFuncSetAttribute(bgemm<false, false, true >, cudaFuncAttributeMaxDynamicSharedMemorySize, SMEMSZ);
    cudaFuncSetAttribute(bgemm<true,  false, false>, cudaFuncAttributeMaxDynamicSharedMemorySize, SMEMSZ);
    cudaFuncSetAttribute(bgemm<false, true,  false>, cudaFuncAttributeMaxDynamicSharedMemorySize, SMEMSZ);
    cudaFuncSetAttribute(bgemm<false, false, false>, cudaFuncAttributeMaxDynamicSharedMemorySize, SMEMSZ);

    const float scale = 0.08838834764831845f; // 1/sqrt(128)

    // --- split x + all weights (one launch) ---
    {
        SplitJobs js;
        js.j[0] = { x,     xh,    xl,    MR*DIM/4 };
        js.j[1] = { w_lq,  wlqh,  wlql,  LQ*DIM/4 };
        js.j[2] = { w_lkv, wlkvh, wlkvl, LKV*DIM/4 };
        js.j[3] = { w_q,   wqh,   wql,   HD*LQ/4 };
        js.j[4] = { w_qr,  wqrh,  wqrl,  HD*LQ/4 };
        js.j[5] = { w_k,   wkh,   wkl,   HD*LKV/4 };
        js.j[6] = { w_v,   wvh,   wvl,   HD*LKV/4 };
        js.j[7] = { w_kr,  wkrh,  wkrl,  HD*DIM/4 };
        js.j[8] = { w_o,   woh,   wol,   DIM*HD/4 };
        split_all<<<dim3((MR*DIM/4 + 255)/256, 9), 256>>>(js);
    }

    // --- projections ---
    // cq = x @ w_lq^T -> split
    bgemm<false, false, true><<<dim3(LQ/64, MR/128, 1), 256, SMEMSZ>>>(
        DIM, xh, xl, DIM, 0, 0, wlqh, wlql, DIM, 0, 0,
        nullptr, nullptr, nullptr, nullptr,
        nullptr, LQ, 0, 0, nullptr, 1.f, 1, cqh, cql);
    // ckv = x @ w_lkv^T -> split
    bgemm<false, false, true><<<dim3(LKV/64, MR/128, 1), 256, SMEMSZ>>>(
        DIM, xh, xl, DIM, 0, 0, wlkvh, wlkvl, DIM, 0, 0,
        nullptr, nullptr, nullptr, nullptr,
        nullptr, LKV, 0, 0, nullptr, 1.f, 1, ckvh, ckvl);
    // qa = cq @ w_q^T -> split
    bgemm<false, false, true><<<dim3(HD/64, MR/128, 1), 256, SMEMSZ>>>(
        LQ, cqh, cql, LQ, 0, 0, wqh, wql, LQ, 0, 0,
        nullptr, nullptr, nullptr, nullptr,
        nullptr, HD, 0, 0, nullptr, 1.f, 1, qah, qal);
    // qr = cq @ w_qr^T + b_qr -> fp32 (pre-rope)
    bgemm<true, false, false><<<dim3(HD/64, MR/128, 1), 256, SMEMSZ>>>(
        LQ, cqh, cql, LQ, 0, 0, wqrh, wqrl, LQ, 0, 0,
        nullptr, nullptr, nullptr, nullptr,
        qr, HD, 0, 0, b_qr, 1.f, 1, nullptr, nullptr);
    // ka = ckv @ w_k^T -> split
    bgemm<false, false, true><<<dim3(HD/64, MR/128, 1), 256, SMEMSZ>>>(
        LKV, ckvh, ckvl, LKV, 0, 0, wkh, wkl, LKV, 0, 0,
        nullptr, nullptr, nullptr, nullptr,
        nullptr, HD, 0, 0, nullptr, 1.f, 1, kah, kal);
    // kr = x @ w_kr^T + b_kr -> fp32 (pre-rope)
    bgemm<true, false, false><<<dim3(HD/64, MR/128, 1), 256, SMEMSZ>>>(
        DIM, xh, xl, DIM, 0, 0, wkrh, wkrl, DIM, 0, 0,
        nullptr, nullptr, nullptr, nullptr,
        kr, HD, 0, 0, b_kr, 1.f, 1, nullptr, nullptr);
    // v = ckv @ w_v^T -> fp32
    bgemm<false, false, false><<<dim3(HD/64, MR/128, 1), 256, SMEMSZ>>>(
        LKV, ckvh, ckvl, LKV, 0, 0, wvh, wvl, LKV, 0, 0,
        nullptr, nullptr, nullptr, nullptr,
        vv, HD, 0, 0, nullptr, 1.f, 1, nullptr, nullptr);

    // --- RoPE + split on qr, kr ---
    {
        long long pairs = (long long)MR * NH * (DH / 2);
        int blocks = (int)((pairs + 255) / 256);
        rope_split<<<blocks, 256>>>(qr, qrh, qrl, fc, fs);
        rope_split<<<blocks, 256>>>(kr, krh, krl, fc, fs);
    }

    // --- transpose V + split ---
    transpose_split<<<dim3(DH/32, SS/32, BB*NH), dim3(32, 8)>>>(vv, vth, vtl);

    // --- scores: sc[z] = (qa.ka^T + qr.kr^T) * scale ---
    {
        long long sQb = (long long)SS * HD;
        long long sQz = DH;
        long long sSb = (long long)NH * SS * SS;
        long long sSz = (long long)SS * SS;
        bgemm<false, true, false><<<dim3(SS/64, SS/128, BB*NH), 256, SMEMSZ>>>(
            DH, qah, qal, HD, sQb, sQz, kah, kal, HD, sQb, sQz,
            qrh, qrl, krh, krl,
            sc, SS, sSb, sSz, nullptr, scale, NH, nullptr, nullptr);
    }

    // --- softmax + split -> P hi/lo ---
    softmax_split<<<BB * NH * SS, 256>>>(sc, ph, pl);

    // --- PV: att = P @ vt^T -> split ---
    {
        long long sPb = (long long)NH * SS * SS;
        long long sPz = (long long)SS * SS;
        long long sVb = (long long)NH * DH * SS;
        long long sVz = (long long)DH * SS;
        long long sCb = (long long)SS * HD;
        long long sCz = DH;
        bgemm<false, false, true><<<dim3(DH/64, SS/128, BB*NH), 256, SMEMSZ>>>(
            SS, ph, pl, SS, sPb, sPz, vth, vtl, SS, sVb, sVz,
            nullptr, nullptr, nullptr, nullptr,
            nullptr, HD, sCb, sCz, nullptr, 1.f, NH, atth, attl);
    }

    // --- out = att @ w_o^T + b_o ---
    bgemm<true, false, false><<<dim3(DIM/64, MR/128, 1), 256, SMEMSZ>>>(
        HD, atth, attl, HD, 0, 0, woh, wol, HD, 0, 0,
        nullptr, nullptr, nullptr, nullptr,
        out, DIM, 0, 0, b_o, 1.f, 1, nullptr, nullptr);

    (void)in_sizes; (void)n_in; (void)out_size;
}

// round 12
// speedup vs baseline: 1.0514x; 1.0514x over previous
#include <cuda_runtime.h>
#include <cuda_bf16.h>
#include <cstdint>

// Problem constants
#define BB   2
#define SS   2048
#define DIM  2048
#define NH   16
#define DH   128
#define LKV  512
#define LQ   1024
#define MR   (BB*SS)    // 4096
#define HD   (NH*DH)    // 2048

// fp32 scratch
__device__ float g_qr [MR*(size_t)HD];
__device__ float g_kr [MR*(size_t)HD];
__device__ float g_v  [MR*(size_t)HD];
__device__ float g_sc [(size_t)BB*NH*SS*SS];   // 512 MB scores

// bf16 hi/lo split buffers
__device__ __nv_bfloat16 g_x_h  [MR*(size_t)DIM],  g_x_l  [MR*(size_t)DIM];
__device__ __nv_bfloat16 g_wlq_h [(size_t)LQ*DIM],  g_wlq_l [(size_t)LQ*DIM];
__device__ __nv_bfloat16 g_wlkv_h[(size_t)LKV*DIM], g_wlkv_l[(size_t)LKV*DIM];
__device__ __nv_bfloat16 g_wq_h [(size_t)HD*LQ],   g_wq_l [(size_t)HD*LQ];
__device__ __nv_bfloat16 g_wqr_h[(size_t)HD*LQ],   g_wqr_l[(size_t)HD*LQ];
__device__ __nv_bfloat16 g_wk_h [(size_t)HD*LKV],  g_wk_l [(size_t)HD*LKV];
__device__ __nv_bfloat16 g_wv_h [(size_t)HD*LKV],  g_wv_l [(size_t)HD*LKV];
__device__ __nv_bfloat16 g_wkr_h[(size_t)HD*DIM],  g_wkr_l[(size_t)HD*DIM];
__device__ __nv_bfloat16 g_wo_h [(size_t)DIM*HD],  g_wo_l [(size_t)DIM*HD];
__device__ __nv_bfloat16 g_cq_h [MR*(size_t)LQ],   g_cq_l [MR*(size_t)LQ];
__device__ __nv_bfloat16 g_ckv_h[MR*(size_t)LKV],  g_ckv_l[MR*(size_t)LKV];
__device__ __nv_bfloat16 g_qa_h [MR*(size_t)HD],   g_qa_l [MR*(size_t)HD];
__device__ __nv_bfloat16 g_qrs_h[MR*(size_t)HD],   g_qrs_l[MR*(size_t)HD];
__device__ __nv_bfloat16 g_ka_h [MR*(size_t)HD],   g_ka_l [MR*(size_t)HD];
__device__ __nv_bfloat16 g_krs_h[MR*(size_t)HD],   g_krs_l[MR*(size_t)HD];
__device__ __nv_bfloat16 g_vt_h [(size_t)BB*NH*DH*SS], g_vt_l [(size_t)BB*NH*DH*SS];
__device__ __nv_bfloat16 g_p_h  [(size_t)BB*NH*SS*SS], g_p_l  [(size_t)BB*NH*SS*SS];
__device__ __nv_bfloat16 g_att_h[MR*(size_t)HD],   g_att_l[MR*(size_t)HD];

// ---------------------------------------------------------------------------
// Helpers
// ---------------------------------------------------------------------------
__device__ __forceinline__ uint32_t smem_u32(const void* p) {
    uint32_t a;
    asm("{ .reg .u64 t; cvta.to.shared.u64 t, %1; cvt.u32.u64 %0, t; }" : "=r"(a) : "l"(p));
    return a;
}
__device__ __forceinline__ void ldm_x4(uint32_t addr, uint32_t r[4]) {
    asm volatile("ldmatrix.sync.aligned.m8n8.x4.shared.b16 {%0,%1,%2,%3}, [%4];"
                 : "=r"(r[0]), "=r"(r[1]), "=r"(r[2]), "=r"(r[3]) : "r"(addr));
}
__device__ __forceinline__ void mma16816(float c[4], const uint32_t a[4],
                                         uint32_t b0, uint32_t b1) {
    asm volatile(
        "mma.sync.aligned.m16n8k16.row.col.f32.bf16.bf16.f32 "
        "{%0,%1,%2,%3}, {%4,%5,%6,%7}, {%8,%9}, {%0,%1,%2,%3};"
        : "+f"(c[0]), "+f"(c[1]), "+f"(c[2]), "+f"(c[3])
        : "r"(a[0]), "r"(a[1]), "r"(a[2]), "r"(a[3]), "r"(b0), "r"(b1));
}
__device__ __forceinline__ uint32_t packbf(float a, float b) {
    uint32_t r;
    asm("cvt.rn.satfinite.bf16x2.f32 %0, %1, %2;" : "=r"(r) : "f"(b), "f"(a));
    return r;
}
__device__ __forceinline__ float lo_of(uint32_t h) { return __uint_as_float(h << 16); }
__device__ __forceinline__ float hi_of(uint32_t h) { return __uint_as_float(h & 0xFFFF0000u); }

__device__ __forceinline__ void cp16(uint32_t dst, const void* src) {
    asm volatile("cp.async.cg.shared.global [%0], [%1], 16;" :: "r"(dst), "l"(src) : "memory");
}
#define CP_COMMIT asm volatile("cp.async.commit_group;" ::: "memory")
#define CP_WAIT0  asm volatile("cp.async.wait_group 0;" ::: "memory")
#define CP_WAIT1  asm volatile("cp.async.wait_group 1;" ::: "memory")

// SMEM per stage: A_hi, A_lo, B_hi, B_lo tiles [128 rows x 32 k], pitch 80B
#define PITCH    80
#define OF_ALO   10240
#define OF_BHI   20480
#define OF_BLO   30720
#define STAGE_SZ 40960
#define NSTAGE   2
#define SMEMSZ   (NSTAGE*STAGE_SZ)     // 81920 -> 2 CTAs/SM (164KB of 227KB)

// ---------------------------------------------------------------------------
// bgemm: C = alpha * A * B^T [+ bias], pre-split bf16 hi/lo inputs.
//   CTA tile 128(M) x 128(N), 256 threads = 8 warps (4M x 2N, warp 32x64).
//   DUAL: continue accumulating A2 * B2^T. SPLITOUT: bf16 hi/lo output.
//   Batched via grid.z. Grid (N/128, M/128, Z). 2-stage cp.async pipeline.
//   3-product bf16 emulation => fp32-level accuracy. 2 CTAs/SM guaranteed.
// ---------------------------------------------------------------------------
template<bool BIAS, bool DUAL, bool SPLITOUT>
__global__ __launch_bounds__(256, 2)
void bgemm(int K,
           const __nv_bfloat16* __restrict__ Ah, const __nv_bfloat16* __restrict__ Al,
           int lda, long long sAb, long long sAz,
           const __nv_bfloat16* __restrict__ Bh, const __nv_bfloat16* __restrict__ Bl,
           int ldb, long long sBb, long long sBz,
           const __nv_bfloat16* __restrict__ A2h, const __nv_bfloat16* __restrict__ A2l,
           const __nv_bfloat16* __restrict__ B2h, const __nv_bfloat16* __restrict__ B2l,
           float* __restrict__ C, int ldc, long long sCb, long long sCz,
           const float* __restrict__ bias, float alpha, int Hdiv,
           __nv_bfloat16* __restrict__ Chi, __nv_bfloat16* __restrict__ Clo)
{
    extern __shared__ __align__(128) char smc[];
    const uint32_t smb = smem_u32(smc);
    const int tid  = threadIdx.x;
    const int lane = tid & 31;
    const int wid  = tid >> 5;
    const int wm   = (wid & 3) * 32;        // warp M offset (0..96)
    const int wn   = (wid >> 2) * 64;       // warp N offset (0 or 64)

    int z = blockIdx.z;
    int zb = z / Hdiv, zh = z - zb * Hdiv;
    const long long offA = zb * sAb + zh * sAz;
    const long long offB = zb * sBb + zh * sBz;
    Ah += offA; Al += offA;
    Bh += offB; Bl += offB;
    if (DUAL) { A2h += offA; A2l += offA; B2h += offB; B2l += offB; }
    const long long offC = zb * sCb + zh * sCz;
    if (SPLITOUT) { Chi += offC; Clo += offC; }
    else          { C   += offC; }

    // staging: each tile 128 rows x 32 k bf16 = 8192B; 256 thr x 2 cp16 each
    const int arow = tid >> 1;
    const int aseg = (tid & 1) * 16;            // bf16 elems (32B per thread)
    const long long aoff = (long long)(blockIdx.y * 128 + arow) * lda + aseg;
    const long long boff = (long long)(blockIdx.x * 128 + arow) * ldb + aseg;
    const uint32_t dstA = smb + arow * PITCH + aseg * 2;
    const uint32_t dstB = smb + OF_BHI + arow * PITCH + aseg * 2;

    float acc[2][8][4];
#pragma unroll
    for (int i = 0; i < 2; i++)
#pragma unroll
        for (int j = 0; j < 8; j++)
#pragma unroll
            for (int k = 0; k < 4; k++) acc[i][j][k] = 0.f;

    const int nch   = K >> 5;
    const int total = DUAL ? nch * 2 : nch;

    auto issue = [&](int c) {
        const __nv_bfloat16 *ah = Ah, *al = Al, *bh = Bh, *bl = Bl;
        int cc = c;
        if (DUAL && c >= nch) { ah = A2h; al = A2l; bh = B2h; bl = B2l; cc = c - nch; }
        const long long ka = aoff + cc * 32;
        const long long kb = boff + cc * 32;
        const uint32_t stg = (c & (NSTAGE - 1)) * STAGE_SZ;
        cp16(dstA + stg,                      ah + ka);
        cp16(dstA + stg + 16,                 ah + ka + 8);
        cp16(dstA + stg + OF_ALO,             al + ka);
        cp16(dstA + stg + OF_ALO + 16,        al + ka + 8);
        cp16(dstB + stg,                      bh + kb);
        cp16(dstB + stg + 16,                 bh + kb + 8);
        cp16(dstB + stg + (OF_BLO - OF_BHI),      bl + kb);
        cp16(dstB + stg + (OF_BLO - OF_BHI) + 16, bl + kb + 8);
    };

    auto COMPUTE = [&](int s) {
        const uint32_t sa = smb + s * STAGE_SZ;
#pragma unroll
        for (int ks = 0; ks < 2; ++ks) {
            const uint32_t colb = ks * 32;
            uint32_t ahi[2][4], alo[2][4];
#pragma unroll
            for (int mt = 0; mt < 2; ++mt) {
                uint32_t addr = sa +
                    (wm + mt * 16 + (lane & 15)) * PITCH + colb + (lane >> 4) * 16;
                ldm_x4(addr, ahi[mt]);
                ldm_x4(addr + OF_ALO, alo[mt]);
            }
#pragma unroll
            for (int np = 0; np < 4; ++np) {
                uint32_t bhi[4], blo[4];
                uint32_t addr = sa + OF_BHI +
                    (wn + np * 16 + (lane & 7) + ((lane >> 4) << 3)) * PITCH +
                    colb + ((lane >> 3) & 1) * 16;
                ldm_x4(addr, bhi);
                ldm_x4(addr + (OF_BLO - OF_BHI), blo);
#pragma unroll
                for (int mt = 0; mt < 2; ++mt)
#pragma unroll
                    for (int ntl = 0; ntl < 2; ++ntl) {
                        float* a = acc[mt][np * 2 + ntl];
                        mma16816(a, ahi[mt], bhi[2 * ntl], bhi[2 * ntl + 1]);
                        mma16816(a, ahi[mt], blo[2 * ntl], blo[2 * ntl + 1]);
                        mma16816(a, alo[mt], bhi[2 * ntl], bhi[2 * ntl + 1]);
                    }
            }
        }
    };

    // 2-stage pipeline, one sync per chunk
    issue(0); CP_COMMIT;
    for (int c = 0; c < total; ++c) {
        if (c + 1 < total) { issue(c + 1); CP_COMMIT; CP_WAIT1; } else { CP_WAIT0; }
        __syncthreads();
        COMPUTE(c & (NSTAGE - 1));
        __syncthreads();
    }

    // epilogue
    const int g = lane >> 2, t = lane & 3;
#pragma unroll
    for (int mt = 0; mt < 2; ++mt) {
        const int r0 = blockIdx.y * 128 + wm + mt * 16 + g;
#pragma unroll
        for (int nt = 0; nt < 8; ++nt) {
            const int col = blockIdx.x * 128 + wn + nt * 8 + t * 2;
            float b0 = 0.f, b1 = 0.f;
            if (BIAS) { b0 = bias[col]; b1 = bias[col + 1]; }
            float2 v0, v1;
            v0.x = alpha * acc[mt][nt][0] + b0;
            v0.y = alpha * acc[mt][nt][1] + b1;
            v1.x = alpha * acc[mt][nt][2] + b0;
            v1.y = alpha * acc[mt][nt][3] + b1;
            if (SPLITOUT) {
                uint32_t h0 = packbf(v0.x, v0.y);
                uint32_t l0 = packbf(v0.x - lo_of(h0), v0.y - hi_of(h0));
                uint32_t h1 = packbf(v1.x, v1.y);
                uint32_t l1 = packbf(v1.x - lo_of(h1), v1.y - hi_of(h1));
                *(uint32_t*)&Chi[(long long)r0 * ldc + col] = h0;
                *(uint32_t*)&Clo[(long long)r0 * ldc + col] = l0;
                *(uint32_t*)&Chi[(long long)(r0 + 8) * ldc + col] = h1;
                *(uint32_t*)&Clo[(long long)(r0 + 8) * ldc + col] = l1;
            } else {
                *(float2*)&C[(long long)r0 * ldc + col] = v0;
                *(float2*)&C[(long long)(r0 + 8) * ldc + col] = v1;
            }
        }
    }
}

// ---------------------------------------------------------------------------
// Split fp32 -> bf16 hi/lo, 9 jobs in one launch (grid.y selects job)
// ---------------------------------------------------------------------------
struct SplitJob  { const float* s; __nv_bfloat16* h; __nv_bfloat16* l; int n4; };
struct SplitJobs { SplitJob j[9]; };

__global__ void split_all(SplitJobs js)
{
    SplitJob job = js.j[blockIdx.y];
    int i = blockIdx.x * blockDim.x + threadIdx.x;
    if (i >= job.n4) return;
    float4 v = ((const float4*)job.s)[i];
    uint32_t h0 = packbf(v.x, v.y), h1 = packbf(v.z, v.w);
    uint32_t l0 = packbf(v.x - lo_of(h0), v.y - hi_of(h0));
    uint32_t l1 = packbf(v.z - lo_of(h1), v.w - hi_of(h1));
    ((uint2*)job.h)[i] = make_uint2(h0, h1);
    ((uint2*)job.l)[i] = make_uint2(l0, l1);
}

// ---------------------------------------------------------------------------
// RoPE + split: read fp32 [B*S, H*DH], rotate, write bf16 hi/lo
// ---------------------------------------------------------------------------
__global__ void rope_split(const float* __restrict__ src,
                           __nv_bfloat16* __restrict__ dh,
                           __nv_bfloat16* __restrict__ dl,
                           const float* __restrict__ fc,
                           const float* __restrict__ fs)
{
    long long idx = (long long)blockIdx.x * blockDim.x + threadIdx.x;
    const long long total = (long long)MR * NH * (DH / 2);
    if (idx >= total) return;
    int i = (int)(idx & 63);
    long long t2 = idx >> 6;
    int h = (int)(t2 % NH);
    long long row = t2 / NH;
    int s = (int)(row % SS);
    float c  = fc[s * 64 + i];
    float sn = fs[s * 64 + i];
    size_t off = (size_t)row * HD + h * DH + 2 * i;
    float e = src[off], o = src[off + 1];
    float e2 = e * c - o * sn;
    float o2 = e * sn + o * c;
    uint32_t hi = packbf(e2, o2);
    uint32_t lo = packbf(e2 - lo_of(hi), o2 - hi_of(hi));
    *(uint32_t*)&dh[off] = hi;
    *(uint32_t*)&dl[off] = lo;
}

// ---------------------------------------------------------------------------
// Transpose V + split: vt[z*DH + d][s] = v[(b*SS+s)*HD + h*DH + d]
// ---------------------------------------------------------------------------
__global__ void transpose_split(const float* __restrict__ v,
                                __nv_bfloat16* __restrict__ vth,
                                __nv_bfloat16* __restrict__ vtl)
{
    __shared__ float t[32][33];
    int z = blockIdx.z;
    int b = z / NH, h = z - b * NH;
    int s0 = blockIdx.y * 32, d0 = blockIdx.x * 32;
    int x = threadIdx.x, y = threadIdx.y;
#pragma unroll
    for (int i = 0; i < 32; i += 8)
        t[y + i][x] = v[((long long)(b * SS + s0 + y + i)) * HD + h * DH + d0 + x];
    __syncthreads();
#pragma unroll
    for (int i = 0; i < 32; i += 8) {
        float val = t[x][y + i];
        __nv_bfloat16 hb = __float2bfloat16(val);
        __nv_bfloat16 lb = __float2bfloat16(val - __bfloat162float(hb));
        size_t off = ((size_t)(z * DH + d0 + y + i)) * SS + s0 + x;
        vth[off] = hb;
        vtl[off] = lb;
    }
}

// ---------------------------------------------------------------------------
// Softmax + split: read fp32 score row (2048), write normalized P bf16 hi/lo.
// ---------------------------------------------------------------------------
__global__ __launch_bounds__(256) void softmax_split(const float* __restrict__ S,
                                                     __nv_bfloat16* __restrict__ Ph,
                                                     __nv_bfloat16* __restrict__ Pl)
{
    const float* p = S + (long long)blockIdx.x * SS;
    uint32_t* oh = (uint32_t*)(Ph + (long long)blockIdx.x * SS);
    uint32_t* ol = (uint32_t*)(Pl + (long long)blockIdx.x * SS);
    const int t = threadIdx.x;
    __shared__ float red[8];

    float2 v[4];
#pragma unroll
    for (int j = 0; j < 4; ++j) v[j] = *(const float2*)&p[2 * t + 512 * j];

    float m = fmaxf(v[0].x, v[0].y);
#pragma unroll
    for (int j = 1; j < 4; ++j) m = fmaxf(m, fmaxf(v[j].x, v[j].y));
#pragma unroll
    for (int o = 16; o > 0; o >>= 1) m = fmaxf(m, __shfl_xor_sync(~0u, m, o));
    if ((t & 31) == 0) red[t >> 5] = m;
    __syncthreads();
    if (t < 32) {
        float mm = red[t & 7];
#pragma unroll
        for (int o = 4; o > 0; o >>= 1) mm = fmaxf(mm, __shfl_xor_sync(~0u, mm, o));
        if (t == 0) red[0] = mm;
    }
    __syncthreads();
    m = red[0];
    __syncthreads();

    float sum = 0.f;
#pragma unroll
    for (int j = 0; j < 4; ++j) {
        v[j].x = __expf(v[j].x - m);
        v[j].y = __expf(v[j].y - m);
        sum += v[j].x + v[j].y;
    }
#pragma unroll
    for (int o = 16; o > 0; o >>= 1) sum += __shfl_xor_sync(~0u, sum, o);
    if ((t & 31) == 0) red[t >> 5] = sum;
    __syncthreads();
    if (t < 32) {
        float ss = red[t & 7];
#pragma unroll
        for (int o = 4; o > 0; o >>= 1) ss += __shfl_xor_sync(~0u, ss, o);
        if (t == 0) red[0] = ss;
    }
    __syncthreads();
    const float inv = 1.0f / red[0];
#pragma unroll
    for (int j = 0; j < 4; ++j) {
        float p0 = v[j].x * inv, p1 = v[j].y * inv;
        uint32_t h = packbf(p0, p1);
        uint32_t l = packbf(p0 - lo_of(h), p1 - hi_of(h));
        oh[t + 256 * j] = h;
        ol[t + 256 * j] = l;
    }
}

// ---------------------------------------------------------------------------

extern "C" void kernel_launch(void* const* d_in, const int* in_sizes, int n_in,
                              void* d_out, int out_size)
{
    const float* x    = (const float*)d_in[0];
    const float* fc   = (const float*)d_in[1];
    const float* fs   = (const float*)d_in[2];
    const float* w_lq = (const float*)d_in[3];
    const float* w_lkv= (const float*)d_in[4];
    const float* w_q  = (const float*)d_in[5];
    const float* w_k  = (const float*)d_in[6];
    const float* w_v  = (const float*)d_in[7];
    const float* w_qr = (const float*)d_in[8];
    const float* b_qr = (const float*)d_in[9];
    const float* w_kr = (const float*)d_in[10];
    const float* b_kr = (const float*)d_in[11];
    const float* w_o  = (const float*)d_in[12];
    const float* b_o  = (const float*)d_in[13];
    float* out = (float*)d_out;

    float *qr, *kr, *vv, *sc;
    cudaGetSymbolAddress((void**)&qr, g_qr);
    cudaGetSymbolAddress((void**)&kr, g_kr);
    cudaGetSymbolAddress((void**)&vv, g_v);
    cudaGetSymbolAddress((void**)&sc, g_sc);

    __nv_bfloat16 *xh, *xl, *wlqh, *wlql, *wlkvh, *wlkvl, *wqh, *wql, *wqrh, *wqrl;
    __nv_bfloat16 *wkh, *wkl, *wvh, *wvl, *wkrh, *wkrl, *woh, *wol;
    __nv_bfloat16 *cqh, *cql, *ckvh, *ckvl, *qah, *qal, *qrh, *qrl, *kah, *kal;
    __nv_bfloat16 *krh, *krl, *vth, *vtl, *ph, *pl, *atth, *attl;
    cudaGetSymbolAddress((void**)&xh,    g_x_h);   cudaGetSymbolAddress((void**)&xl,    g_x_l);
    cudaGetSymbolAddress((void**)&wlqh,  g_wlq_h); cudaGetSymbolAddress((void**)&wlql,  g_wlq_l);
    cudaGetSymbolAddress((void**)&wlkvh, g_wlkv_h);cudaGetSymbolAddress((void**)&wlkvl, g_wlkv_l);
    cudaGetSymbolAddress((void**)&wqh,   g_wq_h);  cudaGetSymbolAddress((void**)&wql,   g_wq_l);
    cudaGetSymbolAddress((void**)&wqrh,  g_wqr_h); cudaGetSymbolAddress((void**)&wqrl,  g_wqr_l);
    cudaGetSymbolAddress((void**)&wkh,   g_wk_h);  cudaGetSymbolAddress((void**)&wkl,   g_wk_l);
    cudaGetSymbolAddress((void**)&wvh,   g_wv_h);  cudaGetSymbolAddress((void**)&wvl,   g_wv_l);
    cudaGetSymbolAddress((void**)&wkrh,  g_wkr_h); cudaGetSymbolAddress((void**)&wkrl,  g_wkr_l);
    cudaGetSymbolAddress((void**)&woh,   g_wo_h);  cudaGetSymbolAddress((void**)&wol,   g_wo_l);
    cudaGetSymbolAddress((void**)&cqh,   g_cq_h);  cudaGetSymbolAddress((void**)&cql,   g_cq_l);
    cudaGetSymbolAddress((void**)&ckvh,  g_ckv_h); cudaGetSymbolAddress((void**)&ckvl,  g_ckv_l);
    cudaGetSymbolAddress((void**)&qah,   g_qa_h);  cudaGetSymbolAddress((void**)&qal,   g_qa_l);
    cudaGetSymbolAddress((void**)&qrh,   g_qrs_h); cudaGetSymbolAddress((void**)&qrl,   g_qrs_l);
    cudaGetSymbolAddress((void**)&kah,   g_ka_h);  cudaGetSymbolAddress((void**)&kal,   g_ka_l);
    cudaGetSymbolAddress((void**)&krh,   g_krs_h); cudaGetSymbolAddress((void**)&krl,   g_krs_l);
    cudaGetSymbolAddress((void**)&vth,   g_vt_h);  cudaGetSymbolAddress((void**)&vtl,   g_vt_l);
    cudaGetSymbolAddress((void**)&ph,    g_p_h);   cudaGetSymbolAddress((void**)&pl,    g_p_l);
    cudaGetSymbolAddress((void**)&atth,  g_att_h); cudaGetSymbolAddress((void**)&attl,  g_att_l);

    cudaFuncSetAttribute(bgemm<false, false, true >, cudaFuncAttributeMaxDynamicSharedMemorySize, SMEMSZ);
    cudaFuncSetAttribute(bgemm<true,  false, false>, cudaFuncAttributeMaxDynamicSharedMemorySize, SMEMSZ);
    cudaFuncSetAttribute(bgemm<false, true,  false>, cudaFuncAttributeMaxDynamicSharedMemorySize, SMEMSZ);
    cudaFuncSetAttribute(bgemm<false, false, false>, cudaFuncAttributeMaxDynamicSharedMemorySize, SMEMSZ);

    const float scale = 0.08838834764831845f; // 1/sqrt(128)

    // --- split x + all weights (one launch) ---
    {
        SplitJobs js;
        js.j[0] = { x,     xh,    xl,    MR*DIM/4 };
        js.j[1] = { w_lq,  wlqh,  wlql,  LQ*DIM/4 };
        js.j[2] = { w_lkv, wlkvh, wlkvl, LKV*DIM/4 };
        js.j[3] = { w_q,   wqh,   wql,   HD*LQ/4 };
        js.j[4] = { w_qr,  wqrh,  wqrl,  HD*LQ/4 };
        js.j[5] = { w_k,   wkh,   wkl,   HD*LKV/4 };
        js.j[6] = { w_v,   wvh,   wvl,   HD*LKV/4 };
        js.j[7] = { w_kr,  wkrh,  wkrl,  HD*DIM/4 };
        js.j[8] = { w_o,   woh,   wol,   DIM*HD/4 };
        split_all<<<dim3((MR*DIM/4 + 255)/256, 9), 256>>>(js);
    }

    // --- projections ---
    // cq = x @ w_lq^T -> split
    bgemm<false, false, true><<<dim3(LQ/128, MR/128, 1), 256, SMEMSZ>>>(
        DIM, xh, xl, DIM, 0, 0, wlqh, wlql, DIM, 0, 0,
        nullptr, nullptr, nullptr, nullptr,
        nullptr, LQ, 0, 0, nullptr, 1.f, 1, cqh, cql);
    // ckv = x @ w_lkv^T -> split
    bgemm<false, false, true><<<dim3(LKV/128, MR/128, 1), 256, SMEMSZ>>>(
        DIM, xh, xl, DIM, 0, 0, wlkvh, wlkvl, DIM, 0, 0,
        nullptr, nullptr, nullptr, nullptr,
        nullptr, LKV, 0, 0, nullptr, 1.f, 1, ckvh, ckvl);
    // qa = cq @ w_q^T -> split
    bgemm<false, false, true><<<dim3(HD/128, MR/128, 1), 256, SMEMSZ>>>(
        LQ, cqh, cql, LQ, 0, 0, wqh, wql, LQ, 0, 0,
        nullptr, nullptr, nullptr, nullptr,
        nullptr, HD, 0, 0, nullptr, 1.f, 1, qah, qal);
    // qr = cq @ w_qr^T + b_qr -> fp32 (pre-rope)
    bgemm<true, false, false><<<dim3(HD/128, MR/128, 1), 256, SMEMSZ>>>(
        LQ, cqh, cql, LQ, 0, 0, wqrh, wqrl, LQ, 0, 0,
        nullptr, nullptr, nullptr, nullptr,
        qr, HD, 0, 0, b_qr, 1.f, 1, nullptr, nullptr);
    // ka = ckv @ w_k^T -> split
    bgemm<false, false, true><<<dim3(HD/128, MR/128, 1), 256, SMEMSZ>>>(
        LKV, ckvh, ckvl, LKV, 0, 0, wkh, wkl, LKV, 0, 0,
        nullptr, nullptr, nullptr, nullptr,
        nullptr, HD, 0, 0, nullptr, 1.f, 1, kah, kal);
    // kr = x @ w_kr^T + b_kr -> fp32 (pre-rope)
    bgemm<true, false, false><<<dim3(HD/128, MR/128, 1), 256, SMEMSZ>>>(
        DIM, xh, xl, DIM, 0, 0, wkrh, wkrl, DIM, 0, 0,
        nullptr, nullptr, nullptr, nullptr,
        kr, HD, 0, 0, b_kr, 1.f, 1, nullptr, nullptr);
    // v = ckv @ w_v^T -> fp32
    bgemm<false, false, false><<<dim3(HD/128, MR/128, 1), 256, SMEMSZ>>>(
        LKV, ckvh, ckvl, LKV, 0, 0, wvh, wvl, LKV, 0, 0,
        nullptr, nullptr, nullptr, nullptr,
        vv, HD, 0, 0, nullptr, 1.f, 1, nullptr, nullptr);

    // --- RoPE + split on qr, kr ---
    {
        long long pairs = (long long)MR * NH * (DH / 2);
        int blocks = (int)((pairs + 255) / 256);
        rope_split<<<blocks, 256>>>(qr, qrh, qrl, fc, fs);
        rope_split<<<blocks, 256>>>(kr, krh, krl, fc, fs);
    }

    // --- transpose V + split ---
    transpose_split<<<dim3(DH/32, SS/32, BB*NH), dim3(32, 8)>>>(vv, vth, vtl);

    // --- scores: sc[z] = (qa.ka^T + qr.kr^T) * scale ---
    {
        long long sQb = (long long)SS * HD;
        long long sQz = DH;
        long long sSb = (long long)NH * SS * SS;
        long long sSz = (long long)SS * SS;
        bgemm<false, true, false><<<dim3(SS/128, SS/128, BB*NH), 256, SMEMSZ>>>(
            DH, qah, qal, HD, sQb, sQz, kah, kal, HD, sQb, sQz,
            qrh, qrl, krh, krl,
            sc, SS, sSb, sSz, nullptr, scale, NH, nullptr, nullptr);
    }

    // --- softmax + split -> P hi/lo ---
    softmax_split<<<BB * NH * SS, 256>>>(sc, ph, pl);

    // --- PV: att = P @ vt^T -> split ---
    {
        long long sPb = (long long)NH * SS * SS;
        long long sPz = (long long)SS * SS;
        long long sVb = (long long)NH * DH * SS;
        long long sVz = (long long)DH * SS;
        long long sCb = (long long)SS * HD;
        long long sCz = DH;
        bgemm<false, false, true><<<dim3(DH/128, SS/128, BB*NH), 256, SMEMSZ>>>(
            SS, ph, pl, SS, sPb, sPz, vth, vtl, SS, sVb, sVz,
            nullptr, nullptr, nullptr, nullptr,
            nullptr, HD, sCb, sCz, nullptr, 1.f, NH, atth, attl);
    }

    // --- out = att @ w_o^T + b_o ---
    bgemm<true, false, false><<<dim3(DIM/128, MR/128, 1), 256, SMEMSZ>>>(
        HD, atth, attl, HD, 0, 0, woh, wol, HD, 0, 0,
        nullptr, nullptr, nullptr, nullptr,
        out, DIM, 0, 0, b_o, 1.f, 1, nullptr, nullptr);

    (void)in_sizes; (void)n_in; (void)out_size;
}

// round 13
// speedup vs baseline: 1.4247x; 1.3550x over previous
#include <cuda_runtime.h>
#include <cuda_fp16.h>
#include <cstdint>

// Problem constants
#define BB   2
#define SS   2048
#define DIM  2048
#define NH   16
#define DH   128
#define LKV  512
#define LQ   1024
#define MR   (BB*SS)    // 4096
#define HD   (NH*DH)    // 2048

// fp32 scratch
__device__ float g_qr [MR*(size_t)HD];
__device__ float g_kr [MR*(size_t)HD];
__device__ float g_v  [MR*(size_t)HD];
__device__ float g_sc [(size_t)BB*NH*SS*SS];   // 512 MB scores

// A-side operands: fp16 hi/lo split
__device__ __half g_x_h  [MR*(size_t)DIM],  g_x_l  [MR*(size_t)DIM];
__device__ __half g_cq_h [MR*(size_t)LQ],   g_cq_l [MR*(size_t)LQ];
__device__ __half g_ckv_h[MR*(size_t)LKV],  g_ckv_l[MR*(size_t)LKV];
__device__ __half g_qa_h [MR*(size_t)HD],   g_qa_l [MR*(size_t)HD];
__device__ __half g_qrs_h[MR*(size_t)HD],   g_qrs_l[MR*(size_t)HD];
__device__ __half g_p_h  [(size_t)BB*NH*SS*SS], g_p_l [(size_t)BB*NH*SS*SS];
__device__ __half g_att_h[MR*(size_t)HD],   g_att_l[MR*(size_t)HD];
// B-side operands: plain fp16
__device__ __half g_wlq [(size_t)LQ*DIM];
__device__ __half g_wlkv[(size_t)LKV*DIM];
__device__ __half g_wq  [(size_t)HD*LQ];
__device__ __half g_wqr [(size_t)HD*LQ];
__device__ __half g_wk  [(size_t)HD*LKV];
__device__ __half g_wv  [(size_t)HD*LKV];
__device__ __half g_wkr [(size_t)HD*DIM];
__device__ __half g_wo  [(size_t)DIM*HD];
__device__ __half g_ka  [MR*(size_t)HD];
__device__ __half g_krs [MR*(size_t)HD];
__device__ __half g_vt  [(size_t)BB*NH*DH*SS];

// ---------------------------------------------------------------------------
// Helpers
// ---------------------------------------------------------------------------
__device__ __forceinline__ uint32_t smem_u32(const void* p) {
    uint32_t a;
    asm("{ .reg .u64 t; cvta.to.shared.u64 t, %1; cvt.u32.u64 %0, t; }" : "=r"(a) : "l"(p));
    return a;
}
__device__ __forceinline__ void ldm_x4(uint32_t addr, uint32_t r[4]) {
    asm volatile("ldmatrix.sync.aligned.m8n8.x4.shared.b16 {%0,%1,%2,%3}, [%4];"
                 : "=r"(r[0]), "=r"(r[1]), "=r"(r[2]), "=r"(r[3]) : "r"(addr));
}
__device__ __forceinline__ void mma_h(float c[4], const uint32_t a[4],
                                      uint32_t b0, uint32_t b1) {
    asm volatile(
        "mma.sync.aligned.m16n8k16.row.col.f32.f16.f16.f32 "
        "{%0,%1,%2,%3}, {%4,%5,%6,%7}, {%8,%9}, {%0,%1,%2,%3};"
        : "+f"(c[0]), "+f"(c[1]), "+f"(c[2]), "+f"(c[3])
        : "r"(a[0]), "r"(a[1]), "r"(a[2]), "r"(a[3]), "r"(b0), "r"(b1));
}
// pack two fp32 -> fp16x2 {low=a, high=b}
__device__ __forceinline__ uint32_t packh(float a, float b) {
    __half2 h = __floats2half2_rn(a, b);
    return *(uint32_t*)&h;
}
__device__ __forceinline__ float h_lo(uint32_t h) {
    __half2 v = *(__half2*)&h;
    return __low2float(v);
}
__device__ __forceinline__ float h_hi(uint32_t h) {
    __half2 v = *(__half2*)&h;
    return __high2float(v);
}

__device__ __forceinline__ void cp16(uint32_t dst, const void* src) {
    asm volatile("cp.async.cg.shared.global [%0], [%1], 16;" :: "r"(dst), "l"(src) : "memory");
}
#define CP_COMMIT asm volatile("cp.async.commit_group;" ::: "memory")
#define CP_WAIT0  asm volatile("cp.async.wait_group 0;" ::: "memory")
#define CP_WAIT1  asm volatile("cp.async.wait_group 1;" ::: "memory")

// SMEM per stage: A_hi, A_lo, B tiles [128 rows x 32 k fp16], pitch 80B
#define PITCH    80
#define OF_ALO   10240
#define OF_B     20480
#define STAGE_SZ 30720
#define NSTAGE   2
#define SMEMSZ   (NSTAGE*STAGE_SZ)     // 61440 -> 2 CTAs/SM comfortably

// Epilogue modes
#define OM_F32   0
#define OM_SPLIT 1
#define OM_HALF  2

// ---------------------------------------------------------------------------
// bgemm: C = alpha * A * B^T [+ bias]
//   A = (Ah + Al) fp16 hi/lo split [M,K]; B plain fp16 [N,K].
//   D = Ah*B^T + Al*B^T  (2 MMAs per k-step: fp32-grade via fp16 split-A)
//   CTA tile 128x128, 256 threads = 8 warps (4M x 2N, warp 32x64).
//   DUAL: continue with A2/B2. OM: fp32 / split-fp16 / plain-fp16 output.
// ---------------------------------------------------------------------------
template<int OM, bool BIAS, bool DUAL>
__global__ __launch_bounds__(256, 2)
void bgemm(int K,
           const __half* __restrict__ Ah, const __half* __restrict__ Al,
           int lda, long long sAb, long long sAz,
           const __half* __restrict__ Bm,
           int ldb, long long sBb, long long sBz,
           const __half* __restrict__ A2h, const __half* __restrict__ A2l,
           const __half* __restrict__ B2,
           float* __restrict__ C, int ldc, long long sCb, long long sCz,
           const float* __restrict__ bias, float alpha, int Hdiv,
           __half* __restrict__ Chi, __half* __restrict__ Clo)
{
    extern __shared__ __align__(128) char smc[];
    const uint32_t smb = smem_u32(smc);
    const int tid  = threadIdx.x;
    const int lane = tid & 31;
    const int wid  = tid >> 5;
    const int wm   = (wid & 3) * 32;        // warp M offset
    const int wn   = (wid >> 2) * 64;       // warp N offset

    int z = blockIdx.z;
    int zb = z / Hdiv, zh = z - zb * Hdiv;
    const long long offA = zb * sAb + zh * sAz;
    const long long offB = zb * sBb + zh * sBz;
    Ah += offA; Al += offA;
    Bm += offB;
    if (DUAL) { A2h += offA; A2l += offA; B2 += offB; }
    const long long offC = zb * sCb + zh * sCz;
    if (OM == OM_F32) C += offC; else { Chi += offC; if (OM == OM_SPLIT) Clo += offC; }

    // staging: each tile 128 rows x 32 k fp16 = 8192B; 256 thr cover w/ 2 cp16
    const int arow = tid >> 1;
    const int aseg = (tid & 1) * 16;            // fp16 elems (32B per thread)
    const long long aoff = (long long)(blockIdx.y * 128 + arow) * lda + aseg;
    const long long boff = (long long)(blockIdx.x * 128 + arow) * ldb + aseg;
    const uint32_t dstA = smb + arow * PITCH + aseg * 2;
    const uint32_t dstB = smb + OF_B + arow * PITCH + aseg * 2;

    float acc[2][8][4];
#pragma unroll
    for (int i = 0; i < 2; i++)
#pragma unroll
        for (int j = 0; j < 8; j++)
#pragma unroll
            for (int k = 0; k < 4; k++) acc[i][j][k] = 0.f;

    const int nch   = K >> 5;
    const int total = DUAL ? nch * 2 : nch;

    auto issue = [&](int c) {
        const __half *ah = Ah, *al = Al, *bm = Bm;
        int cc = c;
        if (DUAL && c >= nch) { ah = A2h; al = A2l; bm = B2; cc = c - nch; }
        const long long ka = aoff + cc * 32;
        const long long kb = boff + cc * 32;
        const uint32_t stg = (c & (NSTAGE - 1)) * STAGE_SZ;
        cp16(dstA + stg,               ah + ka);
        cp16(dstA + stg + 16,          ah + ka + 8);
        cp16(dstA + stg + OF_ALO,      al + ka);
        cp16(dstA + stg + OF_ALO + 16, al + ka + 8);
        cp16(dstB + stg,               bm + kb);
        cp16(dstB + stg + 16,          bm + kb + 8);
    };

    auto COMPUTE = [&](int s) {
        const uint32_t sa = smb + s * STAGE_SZ;
#pragma unroll
        for (int ks = 0; ks < 2; ++ks) {
            const uint32_t colb = ks * 32;
            uint32_t ahi[2][4], alo[2][4];
#pragma unroll
            for (int mt = 0; mt < 2; ++mt) {
                uint32_t addr = sa +
                    (wm + mt * 16 + (lane & 15)) * PITCH + colb + (lane >> 4) * 16;
                ldm_x4(addr, ahi[mt]);
                ldm_x4(addr + OF_ALO, alo[mt]);
            }
#pragma unroll
            for (int np = 0; np < 4; ++np) {
                uint32_t bf[4];
                uint32_t addr = sa + OF_B +
                    (wn + np * 16 + (lane & 7) + ((lane >> 4) << 3)) * PITCH +
                    colb + ((lane >> 3) & 1) * 16;
                ldm_x4(addr, bf);
#pragma unroll
                for (int mt = 0; mt < 2; ++mt)
#pragma unroll
                    for (int ntl = 0; ntl < 2; ++ntl) {
                        float* a = acc[mt][np * 2 + ntl];
                        mma_h(a, ahi[mt], bf[2 * ntl], bf[2 * ntl + 1]);
                        mma_h(a, alo[mt], bf[2 * ntl], bf[2 * ntl + 1]);
                    }
            }
        }
    };

    // 2-stage pipeline, one sync per chunk
    issue(0); CP_COMMIT;
    for (int c = 0; c < total; ++c) {
        if (c + 1 < total) { issue(c + 1); CP_COMMIT; CP_WAIT1; } else { CP_WAIT0; }
        __syncthreads();
        COMPUTE(c & (NSTAGE - 1));
        __syncthreads();
    }

    // epilogue
    const int g = lane >> 2, t = lane & 3;
#pragma unroll
    for (int mt = 0; mt < 2; ++mt) {
        const int r0 = blockIdx.y * 128 + wm + mt * 16 + g;
#pragma unroll
        for (int nt = 0; nt < 8; ++nt) {
            const int col = blockIdx.x * 128 + wn + nt * 8 + t * 2;
            float b0 = 0.f, b1 = 0.f;
            if (BIAS) { b0 = bias[col]; b1 = bias[col + 1]; }
            float2 v0, v1;
            v0.x = alpha * acc[mt][nt][0] + b0;
            v0.y = alpha * acc[mt][nt][1] + b1;
            v1.x = alpha * acc[mt][nt][2] + b0;
            v1.y = alpha * acc[mt][nt][3] + b1;
            if (OM == OM_F32) {
                *(float2*)&C[(long long)r0 * ldc + col] = v0;
                *(float2*)&C[(long long)(r0 + 8) * ldc + col] = v1;
            } else if (OM == OM_HALF) {
                *(uint32_t*)&Chi[(long long)r0 * ldc + col] = packh(v0.x, v0.y);
                *(uint32_t*)&Chi[(long long)(r0 + 8) * ldc + col] = packh(v1.x, v1.y);
            } else {
                uint32_t h0 = packh(v0.x, v0.y);
                uint32_t l0 = packh(v0.x - h_lo(h0), v0.y - h_hi(h0));
                uint32_t h1 = packh(v1.x, v1.y);
                uint32_t l1 = packh(v1.x - h_lo(h1), v1.y - h_hi(h1));
                *(uint32_t*)&Chi[(long long)r0 * ldc + col] = h0;
                *(uint32_t*)&Clo[(long long)r0 * ldc + col] = l0;
                *(uint32_t*)&Chi[(long long)(r0 + 8) * ldc + col] = h1;
                *(uint32_t*)&Clo[(long long)(r0 + 8) * ldc + col] = l1;
            }
        }
    }
}

// ---------------------------------------------------------------------------
// Split fp32 -> fp16: mode 0 = hi/lo split (A-side), mode 1 = plain (B-side)
// ---------------------------------------------------------------------------
struct SplitJob  { const float* s; __half* h; __half* l; int n4; int mode; };
struct SplitJobs { SplitJob j[9]; };

__global__ void split_all(SplitJobs js)
{
    SplitJob job = js.j[blockIdx.y];
    int i = blockIdx.x * blockDim.x + threadIdx.x;
    if (i >= job.n4) return;
    float4 v = ((const float4*)job.s)[i];
    uint32_t h0 = packh(v.x, v.y), h1 = packh(v.z, v.w);
    ((uint2*)job.h)[i] = make_uint2(h0, h1);
    if (job.mode == 0) {
        uint32_t l0 = packh(v.x - h_lo(h0), v.y - h_hi(h0));
        uint32_t l1 = packh(v.z - h_lo(h1), v.w - h_hi(h1));
        ((uint2*)job.l)[i] = make_uint2(l0, l1);
    }
}

// ---------------------------------------------------------------------------
// RoPE: read fp32, rotate; SPLIT=true -> fp16 hi/lo, else plain fp16
// ---------------------------------------------------------------------------
template<bool SPLIT>
__global__ void rope_conv(const float* __restrict__ src,
                          __half* __restrict__ dh,
                          __half* __restrict__ dl,
                          const float* __restrict__ fc,
                          const float* __restrict__ fs)
{
    long long idx = (long long)blockIdx.x * blockDim.x + threadIdx.x;
    const long long total = (long long)MR * NH * (DH / 2);
    if (idx >= total) return;
    int i = (int)(idx & 63);
    long long t2 = idx >> 6;
    int h = (int)(t2 % NH);
    long long row = t2 / NH;
    int s = (int)(row % SS);
    float c  = fc[s * 64 + i];
    float sn = fs[s * 64 + i];
    size_t off = (size_t)row * HD + h * DH + 2 * i;
    float e = src[off], o = src[off + 1];
    float e2 = e * c - o * sn;
    float o2 = e * sn + o * c;
    uint32_t hi = packh(e2, o2);
    *(uint32_t*)&dh[off] = hi;
    if (SPLIT) {
        uint32_t lo = packh(e2 - h_lo(hi), o2 - h_hi(hi));
        *(uint32_t*)&dl[off] = lo;
    }
}

// ---------------------------------------------------------------------------
// Transpose V -> plain fp16: vt[z*DH + d][s] = v[(b*SS+s)*HD + h*DH + d]
// ---------------------------------------------------------------------------
__global__ void transpose_half(const float* __restrict__ v,
                               __half* __restrict__ vt)
{
    __shared__ float t[32][33];
    int z = blockIdx.z;
    int b = z / NH, h = z - b * NH;
    int s0 = blockIdx.y * 32, d0 = blockIdx.x * 32;
    int x = threadIdx.x, y = threadIdx.y;
#pragma unroll
    for (int i = 0; i < 32; i += 8)
        t[y + i][x] = v[((long long)(b * SS + s0 + y + i)) * HD + h * DH + d0 + x];
    __syncthreads();
#pragma unroll
    for (int i = 0; i < 32; i += 8) {
        size_t off = ((size_t)(z * DH + d0 + y + i)) * SS + s0 + x;
        vt[off] = __float2half_rn(t[x][y + i]);
    }
}

// ---------------------------------------------------------------------------
// Softmax: fp32 row (2048) -> normalized P as fp16 hi/lo (A-side operand)
// ---------------------------------------------------------------------------
__global__ __launch_bounds__(256) void softmax_split(const float* __restrict__ S,
                                                     __half* __restrict__ Ph,
                                                     __half* __restrict__ Pl)
{
    const float* p = S + (long long)blockIdx.x * SS;
    uint32_t* oh = (uint32_t*)(Ph + (long long)blockIdx.x * SS);
    uint32_t* ol = (uint32_t*)(Pl + (long long)blockIdx.x * SS);
    const int t = threadIdx.x;
    __shared__ float red[8];

    float2 v[4];
#pragma unroll
    for (int j = 0; j < 4; ++j) v[j] = *(const float2*)&p[2 * t + 512 * j];

    float m = fmaxf(v[0].x, v[0].y);
#pragma unroll
    for (int j = 1; j < 4; ++j) m = fmaxf(m, fmaxf(v[j].x, v[j].y));
#pragma unroll
    for (int o = 16; o > 0; o >>= 1) m = fmaxf(m, __shfl_xor_sync(~0u, m, o));
    if ((t & 31) == 0) red[t >> 5] = m;
    __syncthreads();
    if (t < 32) {
        float mm = red[t & 7];
#pragma unroll
        for (int o = 4; o > 0; o >>= 1) mm = fmaxf(mm, __shfl_xor_sync(~0u, mm, o));
        if (t == 0) red[0] = mm;
    }
    __syncthreads();
    m = red[0];
    __syncthreads();

    float sum = 0.f;
#pragma unroll
    for (int j = 0; j < 4; ++j) {
        v[j].x = __expf(v[j].x - m);
        v[j].y = __expf(v[j].y - m);
        sum += v[j].x + v[j].y;
    }
#pragma unroll
    for (int o = 16; o > 0; o >>= 1) sum += __shfl_xor_sync(~0u, sum, o);
    if ((t & 31) == 0) red[t >> 5] = sum;
    __syncthreads();
    if (t < 32) {
        float ss = red[t & 7];
#pragma unroll
        for (int o = 4; o > 0; o >>= 1) ss += __shfl_xor_sync(~0u, ss, o);
        if (t == 0) red[0] = ss;
    }
    __syncthreads();
    const float inv = 1.0f / red[0];
#pragma unroll
    for (int j = 0; j < 4; ++j) {
        float p0 = v[j].x * inv, p1 = v[j].y * inv;
        uint32_t h = packh(p0, p1);
        uint32_t l = packh(p0 - h_lo(h), p1 - h_hi(h));
        oh[t + 256 * j] = h;
        ol[t + 256 * j] = l;
    }
}

// ---------------------------------------------------------------------------

extern "C" void kernel_launch(void* const* d_in, const int* in_sizes, int n_in,
                              void* d_out, int out_size)
{
    const float* x    = (const float*)d_in[0];
    const float* fc   = (const float*)d_in[1];
    const float* fs   = (const float*)d_in[2];
    const float* w_lq = (const float*)d_in[3];
    const float* w_lkv= (const float*)d_in[4];
    const float* w_q  = (const float*)d_in[5];
    const float* w_k  = (const float*)d_in[6];
    const float* w_v  = (const float*)d_in[7];
    const float* w_qr = (const float*)d_in[8];
    const float* b_qr = (const float*)d_in[9];
    const float* w_kr = (const float*)d_in[10];
    const float* b_kr = (const float*)d_in[11];
    const float* w_o  = (const float*)d_in[12];
    const float* b_o  = (const float*)d_in[13];
    float* out = (float*)d_out;

    float *qr, *kr, *vv, *sc;
    cudaGetSymbolAddress((void**)&qr, g_qr);
    cudaGetSymbolAddress((void**)&kr, g_kr);
    cudaGetSymbolAddress((void**)&vv, g_v);
    cudaGetSymbolAddress((void**)&sc, g_sc);

    __half *xh, *xl, *cqh, *cql, *ckvh, *ckvl, *qah, *qal, *qrh, *qrl;
    __half *ph, *pl, *atth, *attl;
    __half *wlq, *wlkv, *wq, *wqr, *wk, *wv, *wkr, *wo, *ka, *krs, *vt;
    cudaGetSymbolAddress((void**)&xh,   g_x_h);   cudaGetSymbolAddress((void**)&xl,   g_x_l);
    cudaGetSymbolAddress((void**)&cqh,  g_cq_h);  cudaGetSymbolAddress((void**)&cql,  g_cq_l);
    cudaGetSymbolAddress((void**)&ckvh, g_ckv_h); cudaGetSymbolAddress((void**)&ckvl, g_ckv_l);
    cudaGetSymbolAddress((void**)&qah,  g_qa_h);  cudaGetSymbolAddress((void**)&qal,  g_qa_l);
    cudaGetSymbolAddress((void**)&qrh,  g_qrs_h); cudaGetSymbolAddress((void**)&qrl,  g_qrs_l);
    cudaGetSymbolAddress((void**)&ph,   g_p_h);   cudaGetSymbolAddress((void**)&pl,   g_p_l);
    cudaGetSymbolAddress((void**)&atth, g_att_h); cudaGetSymbolAddress((void**)&attl, g_att_l);
    cudaGetSymbolAddress((void**)&wlq,  g_wlq);
    cudaGetSymbolAddress((void**)&wlkv, g_wlkv);
    cudaGetSymbolAddress((void**)&wq,   g_wq);
    cudaGetSymbolAddress((void**)&wqr,  g_wqr);
    cudaGetSymbolAddress((void**)&wk,   g_wk);
    cudaGetSymbolAddress((void**)&wv,   g_wv);
    cudaGetSymbolAddress((void**)&wkr,  g_wkr);
    cudaGetSymbolAddress((void**)&wo,   g_wo);
    cudaGetSymbolAddress((void**)&ka,   g_ka);
    cudaGetSymbolAddress((void**)&krs,  g_krs);
    cudaGetSymbolAddress((void**)&vt,   g_vt);

    cudaFuncSetAttribute(bgemm<OM_SPLIT, false, false>, cudaFuncAttributeMaxDynamicSharedMemorySize, SMEMSZ);
    cudaFuncSetAttribute(bgemm<OM_HALF,  false, false>, cudaFuncAttributeMaxDynamicSharedMemorySize, SMEMSZ);
    cudaFuncSetAttribute(bgemm<OM_F32,   true,  false>, cudaFuncAttributeMaxDynamicSharedMemorySize, SMEMSZ);
    cudaFuncSetAttribute(bgemm<OM_F32,   false, false>, cudaFuncAttributeMaxDynamicSharedMemorySize, SMEMSZ);
    cudaFuncSetAttribute(bgemm<OM_F32,   false, true >, cudaFuncAttributeMaxDynamicSharedMemorySize, SMEMSZ);

    const float scale = 0.08838834764831845f; // 1/sqrt(128)

    // --- convert x + all weights to fp16 (x split, weights plain) ---
    {
        SplitJobs js;
        js.j[0] = { x,     xh,   xl,      MR*DIM/4, 0 };
        js.j[1] = { w_lq,  wlq,  nullptr, LQ*DIM/4, 1 };
        js.j[2] = { w_lkv, wlkv, nullptr, LKV*DIM/4, 1 };
        js.j[3] = { w_q,   wq,   nullptr, HD*LQ/4, 1 };
        js.j[4] = { w_qr,  wqr,  nullptr, HD*LQ/4, 1 };
        js.j[5] = { w_k,   wk,   nullptr, HD*LKV/4, 1 };
        js.j[6] = { w_v,   wv,   nullptr, HD*LKV/4, 1 };
        js.j[7] = { w_kr,  wkr,  nullptr, HD*DIM/4, 1 };
        js.j[8] = { w_o,   wo,   nullptr, DIM*HD/4, 1 };
        split_all<<<dim3((MR*DIM/4 + 255)/256, 9), 256>>>(js);
    }

    // --- projections ---
    // cq = x @ w_lq^T -> split
    bgemm<OM_SPLIT, false, false><<<dim3(LQ/128, MR/128, 1), 256, SMEMSZ>>>(
        DIM, xh, xl, DIM, 0, 0, wlq, DIM, 0, 0,
        nullptr, nullptr, nullptr,
        nullptr, LQ, 0, 0, nullptr, 1.f, 1, cqh, cql);
    // ckv = x @ w_lkv^T -> split
    bgemm<OM_SPLIT, false, false><<<dim3(LKV/128, MR/128, 1), 256, SMEMSZ>>>(
        DIM, xh, xl, DIM, 0, 0, wlkv, DIM, 0, 0,
        nullptr, nullptr, nullptr,
        nullptr, LKV, 0, 0, nullptr, 1.f, 1, ckvh, ckvl);
    // qa = cq @ w_q^T -> split
    bgemm<OM_SPLIT, false, false><<<dim3(HD/128, MR/128, 1), 256, SMEMSZ>>>(
        LQ, cqh, cql, LQ, 0, 0, wq, LQ, 0, 0,
        nullptr, nullptr, nullptr,
        nullptr, HD, 0, 0, nullptr, 1.f, 1, qah, qal);
    // qr = cq @ w_qr^T + b_qr -> fp32 (pre-rope)
    bgemm<OM_F32, true, false><<<dim3(HD/128, MR/128, 1), 256, SMEMSZ>>>(
        LQ, cqh, cql, LQ, 0, 0, wqr, LQ, 0, 0,
        nullptr, nullptr, nullptr,
        qr, HD, 0, 0, b_qr, 1.f, 1, nullptr, nullptr);
    // ka = ckv @ w_k^T -> plain fp16 (B-side for scores)
    bgemm<OM_HALF, false, false><<<dim3(HD/128, MR/128, 1), 256, SMEMSZ>>>(
        LKV, ckvh, ckvl, LKV, 0, 0, wk, LKV, 0, 0,
        nullptr, nullptr, nullptr,
        nullptr, HD, 0, 0, nullptr, 1.f, 1, ka, nullptr);
    // kr = x @ w_kr^T + b_kr -> fp32 (pre-rope)
    bgemm<OM_F32, true, false><<<dim3(HD/128, MR/128, 1), 256, SMEMSZ>>>(
        DIM, xh, xl, DIM, 0, 0, wkr, DIM, 0, 0,
        nullptr, nullptr, nullptr,
        kr, HD, 0, 0, b_kr, 1.f, 1, nullptr, nullptr);
    // v = ckv @ w_v^T -> fp32 (pre-transpose)
    bgemm<OM_F32, false, false><<<dim3(HD/128, MR/128, 1), 256, SMEMSZ>>>(
        LKV, ckvh, ckvl, LKV, 0, 0, wv, LKV, 0, 0,
        nullptr, nullptr, nullptr,
        vv, HD, 0, 0, nullptr, 1.f, 1, nullptr, nullptr);

    // --- RoPE: qr -> split (A-side), kr -> plain (B-side) ---
    {
        long long pairs = (long long)MR * NH * (DH / 2);
        int blocks = (int)((pairs + 255) / 256);
        rope_conv<true ><<<blocks, 256>>>(qr, qrh, qrl, fc, fs);
        rope_conv<false><<<blocks, 256>>>(kr, krs, nullptr, fc, fs);
    }

    // --- transpose V -> plain fp16 ---
    transpose_half<<<dim3(DH/32, SS/32, BB*NH), dim3(32, 8)>>>(vv, vt);

    // --- scores: sc[z] = (qa.ka^T + qr.kr^T) * scale ---
    {
        long long sQb = (long long)SS * HD;
        long long sQz = DH;
        long long sSb = (long long)NH * SS * SS;
        long long sSz = (long long)SS * SS;
        bgemm<OM_F32, false, true><<<dim3(SS/128, SS/128, BB*NH), 256, SMEMSZ>>>(
            DH, qah, qal, HD, sQb, sQz, ka, HD, sQb, sQz,
            qrh, qrl, krs,
            sc, SS, sSb, sSz, nullptr, scale, NH, nullptr, nullptr);
    }

    // --- softmax -> P fp16 hi/lo ---
    softmax_split<<<BB * NH * SS, 256>>>(sc, ph, pl);

    // --- PV: att = P @ vt^T -> split (A-side for out projection) ---
    {
        long long sPb = (long long)NH * SS * SS;
        long long sPz = (long long)SS * SS;
        long long sVb = (long long)NH * DH * SS;
        long long sVz = (long long)DH * SS;
        long long sCb = (long long)SS * HD;
        long long sCz = DH;
        bgemm<OM_SPLIT, false, false><<<dim3(DH/128, SS/128, BB*NH), 256, SMEMSZ>>>(
            SS, ph, pl, SS, sPb, sPz, vt, SS, sVb, sVz,
            nullptr, nullptr, nullptr,
            nullptr, HD, sCb, sCz, nullptr, 1.f, NH, atth, attl);
    }

    // --- out = att @ w_o^T + b_o ---
    bgemm<OM_F32, true, false><<<dim3(DIM/128, MR/128, 1), 256, SMEMSZ>>>(
        HD, atth, attl, HD, 0, 0, wo, HD, 0, 0,
        nullptr, nullptr, nullptr,
        out, DIM, 0, 0, b_o, 1.f, 1, nullptr, nullptr);

    (void)in_sizes; (void)n_in; (void)out_size;
}